// round 13
// baseline (speedup 1.0000x reference)
#include <cuda_runtime.h>
#include <cuda_bf16.h>
#include <math.h>

#define FULL_MASK 0xffffffffu

// In-register butterfly: (a,b) -> (a+b, a-b)
__device__ __forceinline__ void bfly(float &a, float &b) {
    float t = a;
    a = t + b;
    b = t - b;
}

// Warp-level FWHT-256, unscaled.
// Element index mapping: e = ((r>>2)<<7) | (lane<<2) | (r&3), r = register 0..7.
// Bits 0,1,7 are in-register butterflies; bits 2..6 are SHFL+FFMA stages
// (v' = sgn*v + peer, sgn = +/-1 exact, so the math is exact).
__device__ __forceinline__ void fwht_warp(float v[8], const float sgn[5]) {
    bfly(v[0], v[1]); bfly(v[2], v[3]); bfly(v[4], v[5]); bfly(v[6], v[7]);
    bfly(v[0], v[2]); bfly(v[1], v[3]); bfly(v[4], v[6]); bfly(v[5], v[7]);
    bfly(v[0], v[4]); bfly(v[1], v[5]); bfly(v[2], v[6]); bfly(v[3], v[7]);
    #pragma unroll
    for (int j = 0; j < 5; ++j) {
        const int m = 1 << j;
        const float s = sgn[j];
        #pragma unroll
        for (int i = 0; i < 8; ++i) {
            float p = __shfl_xor_sync(FULL_MASK, v[i], m);
            v[i] = fmaf(s, v[i], p);
        }
    }
}

// Warp max of finite fp32 via monotonic float->int mapping + redux.sync.max.s32
// (sm_103 supports integer redux; the f32 variant does not exist here).
__device__ __forceinline__ float warp_redux_max(float x) {
    int b = __float_as_int(x);
    int k = b ^ ((b >> 31) & 0x7fffffff);
    int r;
    asm("redux.sync.max.s32 %0, %1, 0xffffffff;" : "=r"(r) : "r"(k));
    r = r ^ ((r >> 31) & 0x7fffffff);
    return __int_as_float(r);
}

__device__ __forceinline__ float warp_sum(float x) {
    #pragma unroll
    for (int s = 16; s >= 1; s >>= 1)
        x += __shfl_xor_sync(FULL_MASK, x, s);
    return x;
}

#define LOG2E 1.4426950408889634f
#define LN2   0.6931471805599453f

// One warp per row. Row length 256 = 8 floats per lane.
// occ 8 blocks/SM (32 regs), per-t float4 load pairs (last-use hint),
// evict-first streaming stores — the converged-best configuration:
// DRAM 80.3% (6.37 TB/s), bound by HBM mixed read/write efficiency.
__global__ __launch_bounds__(256, 8)
void GroupRecombine_77137612636750_kernel(
    const float* __restrict__ beta_0,
    const float* __restrict__ beta_1,
    const float* __restrict__ masked_k,
    float* __restrict__ out,
    int batch)
{
    const int gw  = (int)((blockIdx.x * (unsigned)blockDim.x + threadIdx.x) >> 5);
    if (gw >= batch) return;
    const int lid = threadIdx.x & 31;

    float sgn[5];
    #pragma unroll
    for (int j = 0; j < 5; ++j)
        sgn[j] = (lid & (1 << j)) ? -1.0f : 1.0f;

    const size_t row     = (size_t)gw * 256;
    const size_t ostride = (size_t)batch * 256;
    const size_t off1    = row + (size_t)lid * 4;
    const size_t off2    = off1 + 128;

    const float* ins[3] = { beta_0, beta_1, masked_k };

    // Scale folding: (2^(-4/3))^3 * 2^-4 = 2^-8 applied once at the end.
    const float S_ALL = 0.00390625f;

    float prod[8];

    #pragma unroll
    for (int t = 0; t < 3; ++t) {
        // last-use loads: data is read exactly once; let L2 drop it immediately.
        const float4 a = __ldlu(reinterpret_cast<const float4*>(ins[t] + off1));
        const float4 c = __ldlu(reinterpret_cast<const float4*>(ins[t] + off2));
        float v[8] = { a.x, a.y, a.z, a.w, c.x, c.y, c.z, c.w };

        // log_softmax of the raw input row
        float m = v[0];
        #pragma unroll
        for (int i = 1; i < 8; ++i) m = fmaxf(m, v[i]);
        m = warp_redux_max(m);

        const float b = -m * LOG2E;          // exp(v-m) = exp2(v*log2e + b)
        float s = 0.f;
        #pragma unroll
        for (int i = 0; i < 8; ++i) s += exp2f(fmaf(v[i], LOG2E, b));
        s = warp_sum(s);
        const float lse = fmaf(LN2, __log2f(s), m);

        float4 o1 = { v[0] - lse, v[1] - lse, v[2] - lse, v[3] - lse };
        float4 o2 = { v[4] - lse, v[5] - lse, v[6] - lse, v[7] - lse };
        __stcs(reinterpret_cast<float4*>(out + (size_t)t * ostride + off1), o1);
        __stcs(reinterpret_cast<float4*>(out + (size_t)t * ostride + off2), o2);

        // FWHT (unscaled), accumulate product
        fwht_warp(v, sgn);
        #pragma unroll
        for (int i = 0; i < 8; ++i)
            prod[i] = (t == 0) ? v[i] : prod[i] * v[i];
    }

    // final transform of the product + folded scaling
    fwht_warp(prod, sgn);
    #pragma unroll
    for (int i = 0; i < 8; ++i) prod[i] *= S_ALL;

    // log_softmax of the result (post-convolution values can be large: keep max)
    float m = prod[0];
    #pragma unroll
    for (int i = 1; i < 8; ++i) m = fmaxf(m, prod[i]);
    m = warp_redux_max(m);

    const float b = -m * LOG2E;
    float s = 0.f;
    #pragma unroll
    for (int i = 0; i < 8; ++i) s += exp2f(fmaf(prod[i], LOG2E, b));
    s = warp_sum(s);
    const float lse = fmaf(LN2, __log2f(s), m);

    float4 o1 = { prod[0] - lse, prod[1] - lse, prod[2] - lse, prod[3] - lse };
    float4 o2 = { prod[4] - lse, prod[5] - lse, prod[6] - lse, prod[7] - lse };
    __stcs(reinterpret_cast<float4*>(out + 3 * ostride + off1), o1);
    __stcs(reinterpret_cast<float4*>(out + 3 * ostride + off2), o2);
}

extern "C" void kernel_launch(void* const* d_in, const int* in_sizes, int n_in,
                              void* d_out, int out_size)
{
    const float* beta_0   = (const float*)d_in[0];
    const float* beta_1   = (const float*)d_in[1];
    const float* masked_k = (const float*)d_in[2];
    float* out = (float*)d_out;

    const int batch = in_sizes[0] / 256;
    const int warps_per_block = 8;
    const int blocks = (batch + warps_per_block - 1) / warps_per_block;

    GroupRecombine_77137612636750_kernel<<<blocks, 256>>>(
        beta_0, beta_1, masked_k, out, batch);
}

// round 14
// speedup vs baseline: 1.0047x; 1.0047x over previous
#include <cuda_runtime.h>
#include <cuda_bf16.h>
#include <math.h>

#define FULL_MASK 0xffffffffu

// In-register butterfly: (a,b) -> (a+b, a-b)
__device__ __forceinline__ void bfly(float &a, float &b) {
    float t = a;
    a = t + b;
    b = t - b;
}

// Warp-level FWHT-256, unscaled.
// Element index mapping: e = ((r>>2)<<7) | (lane<<2) | (r&3), r = register 0..7.
// Bits 0,1,7 are in-register butterflies; bits 2..6 are SHFL+FFMA stages
// (v' = sgn*v + peer, sgn = +/-1 exact, so the math is exact).
__device__ __forceinline__ void fwht_warp(float v[8], const float sgn[5]) {
    bfly(v[0], v[1]); bfly(v[2], v[3]); bfly(v[4], v[5]); bfly(v[6], v[7]);
    bfly(v[0], v[2]); bfly(v[1], v[3]); bfly(v[4], v[6]); bfly(v[5], v[7]);
    bfly(v[0], v[4]); bfly(v[1], v[5]); bfly(v[2], v[6]); bfly(v[3], v[7]);
    #pragma unroll
    for (int j = 0; j < 5; ++j) {
        const int m = 1 << j;
        const float s = sgn[j];
        #pragma unroll
        for (int i = 0; i < 8; ++i) {
            float p = __shfl_xor_sync(FULL_MASK, v[i], m);
            v[i] = fmaf(s, v[i], p);
        }
    }
}

// Warp max of finite fp32 via monotonic float->int mapping + redux.sync.max.s32
// (sm_103 supports integer redux; the f32 variant does not exist here).
__device__ __forceinline__ float warp_redux_max(float x) {
    int b = __float_as_int(x);
    int k = b ^ ((b >> 31) & 0x7fffffff);
    int r;
    asm("redux.sync.max.s32 %0, %1, 0xffffffff;" : "=r"(r) : "r"(k));
    r = r ^ ((r >> 31) & 0x7fffffff);
    return __int_as_float(r);
}

__device__ __forceinline__ float warp_sum(float x) {
    #pragma unroll
    for (int s = 16; s >= 1; s >>= 1)
        x += __shfl_xor_sync(FULL_MASK, x, s);
    return x;
}

#define LOG2E 1.4426950408889634f
#define LN2   0.6931471805599453f

// One warp per row. Row length 256 = 8 floats per lane.
// occ 8 blocks/SM (32 regs), per-t float4 load pairs (streaming hint),
// evict-first streaming stores — the converged-best configuration:
// DRAM ~80% (6.37 TB/s), bound by HBM mixed read/write efficiency.
__global__ __launch_bounds__(256, 8)
void GroupRecombine_77137612636750_kernel(
    const float* __restrict__ beta_0,
    const float* __restrict__ beta_1,
    const float* __restrict__ masked_k,
    float* __restrict__ out,
    int batch)
{
    const int gw  = (int)((blockIdx.x * (unsigned)blockDim.x + threadIdx.x) >> 5);
    if (gw >= batch) return;
    const int lid = threadIdx.x & 31;

    float sgn[5];
    #pragma unroll
    for (int j = 0; j < 5; ++j)
        sgn[j] = (lid & (1 << j)) ? -1.0f : 1.0f;

    const size_t row     = (size_t)gw * 256;
    const size_t ostride = (size_t)batch * 256;
    const size_t off1    = row + (size_t)lid * 4;
    const size_t off2    = off1 + 128;

    const float* ins[3] = { beta_0, beta_1, masked_k };

    // Scale folding: (2^(-4/3))^3 * 2^-4 = 2^-8 applied once at the end.
    const float S_ALL = 0.00390625f;

    float prod[8];

    #pragma unroll
    for (int t = 0; t < 3; ++t) {
        const float4 a = __ldcs(reinterpret_cast<const float4*>(ins[t] + off1));
        const float4 c = __ldcs(reinterpret_cast<const float4*>(ins[t] + off2));
        float v[8] = { a.x, a.y, a.z, a.w, c.x, c.y, c.z, c.w };

        // log_softmax of the raw input row
        float m = v[0];
        #pragma unroll
        for (int i = 1; i < 8; ++i) m = fmaxf(m, v[i]);
        m = warp_redux_max(m);

        const float b = -m * LOG2E;          // exp(v-m) = exp2(v*log2e + b)
        float s = 0.f;
        #pragma unroll
        for (int i = 0; i < 8; ++i) s += exp2f(fmaf(v[i], LOG2E, b));
        s = warp_sum(s);
        const float lse = fmaf(LN2, __log2f(s), m);

        float4 o1 = { v[0] - lse, v[1] - lse, v[2] - lse, v[3] - lse };
        float4 o2 = { v[4] - lse, v[5] - lse, v[6] - lse, v[7] - lse };
        __stcs(reinterpret_cast<float4*>(out + (size_t)t * ostride + off1), o1);
        __stcs(reinterpret_cast<float4*>(out + (size_t)t * ostride + off2), o2);

        // FWHT (unscaled), accumulate product
        fwht_warp(v, sgn);
        #pragma unroll
        for (int i = 0; i < 8; ++i)
            prod[i] = (t == 0) ? v[i] : prod[i] * v[i];
    }

    // final transform of the product + folded scaling
    fwht_warp(prod, sgn);
    #pragma unroll
    for (int i = 0; i < 8; ++i) prod[i] *= S_ALL;

    // log_softmax of the result (post-convolution values can be large: keep max)
    float m = prod[0];
    #pragma unroll
    for (int i = 1; i < 8; ++i) m = fmaxf(m, prod[i]);
    m = warp_redux_max(m);

    const float b = -m * LOG2E;
    float s = 0.f;
    #pragma unroll
    for (int i = 0; i < 8; ++i) s += exp2f(fmaf(prod[i], LOG2E, b));
    s = warp_sum(s);
    const float lse = fmaf(LN2, __log2f(s), m);

    float4 o1 = { prod[0] - lse, prod[1] - lse, prod[2] - lse, prod[3] - lse };
    float4 o2 = { prod[4] - lse, prod[5] - lse, prod[6] - lse, prod[7] - lse };
    __stcs(reinterpret_cast<float4*>(out + 3 * ostride + off1), o1);
    __stcs(reinterpret_cast<float4*>(out + 3 * ostride + off2), o2);
}

extern "C" void kernel_launch(void* const* d_in, const int* in_sizes, int n_in,
                              void* d_out, int out_size)
{
    const float* beta_0   = (const float*)d_in[0];
    const float* beta_1   = (const float*)d_in[1];
    const float* masked_k = (const float*)d_in[2];
    float* out = (float*)d_out;

    const int batch = in_sizes[0] / 256;
    const int warps_per_block = 8;
    const int blocks = (batch + warps_per_block - 1) / warps_per_block;

    GroupRecombine_77137612636750_kernel<<<blocks, 256>>>(
        beta_0, beta_1, masked_k, out, batch);
}